// round 3
// baseline (speedup 1.0000x reference)
#include <cuda_runtime.h>
#include <cuda_fp16.h>

#define Bn 4096
#define Sn 64
#define Un 128
#define Mn 32
#define NUNF 6
#define EPSF 1e-8f

// ---- scratch (static device arrays; no allocation) ----
// sigmoid(sig*(v-mu)) = 0.5 + 0.5*tanh(0.5*sig*v - 0.5*sig*mu)
// Packed half2 recurrent params, laid out per (src s, lane): lane owns dst 4*lane..4*lane+3.
__device__ unsigned g_ABh[Un*32*4];  // {a01,a23,b01,b23}
__device__ unsigned g_Wh [Un*32*2];  // {w01,w23}  w = 0.5*w*mask*erev
__device__ float g_As[Sn*Un];
__device__ float g_Bs[Sn*Un];
__device__ float g_Ws[Sn*Un];
__device__ float g_nbase[Un];
__device__ float g_dbase[Un];
__device__ float g_snum[Bn*Un];
__device__ float g_sden[Bn*Un];

__device__ __forceinline__ float ftanh(float x) {
    float t; asm("tanh.approx.f32 %0, %1;" : "=f"(t) : "f"(x));
    return t;
}
__device__ __forceinline__ __half2 tanh2(__half2 x) {
    unsigned xi = *(unsigned*)&x, ri;
    asm("tanh.approx.f16x2 %0, %1;" : "=r"(ri) : "r"(xi));
    return *(__half2*)&ri;
}
__device__ __forceinline__ unsigned splat_h(float x) {
    unsigned r; asm("cvt.rn.f16x2.f32 %0, %1, %1;" : "=r"(r) : "f"(x));
    return r;
}
__device__ __forceinline__ unsigned packh2(float a, float b) {
    __half2 h = __floats2half2_rn(a, b);   // lo=a, hi=b
    return *(unsigned*)&h;
}
__device__ __forceinline__ __half2 ash2(unsigned u) { return *(__half2*)&u; }

// ---- 1) fold constants ----
__global__ void prep_kernel(const float* __restrict__ sigma, const float* __restrict__ mu,
                            const float* __restrict__ w,     const float* __restrict__ erev,
                            const float* __restrict__ mask,
                            const float* __restrict__ ssig,  const float* __restrict__ smu,
                            const float* __restrict__ sw,    const float* __restrict__ serev,
                            const float* __restrict__ smask) {
    int i = blockIdx.x * 256 + threadIdx.x;
    if (i < Un*Un/2) {              // one thread per dst-pair
        int s = i >> 6, dp = i & 63;
        int lane = dp >> 1, hi = dp & 1;
        int e = s*Un + dp*2;
        float a0 = 0.5f*sigma[e],   a1 = 0.5f*sigma[e+1];
        float b0 = -a0*mu[e],       b1 = -a1*mu[e+1];
        float w0 = 0.5f*w[e]*mask[e]*erev[e];
        float w1 = 0.5f*w[e+1]*mask[e+1]*erev[e+1];
        int base = (s*32 + lane)*4;
        g_ABh[base + hi]     = packh2(a0, a1);
        g_ABh[base + 2 + hi] = packh2(b0, b1);
        g_Wh[(s*32 + lane)*2 + hi] = packh2(w0, w1);
    }
    if (i < Sn*Un) {
        float s = 0.5f * ssig[i];
        g_As[i] = s;
        g_Bs[i] = -s * smu[i];
        g_Ws[i] = 0.5f * sw[i] * smask[i] * serev[i];
    }
}

// ---- 1b) per-dst constant bases (reads raw inputs; independent of prep) ----
__global__ void base_kernel(const float* __restrict__ gleak, const float* __restrict__ vleak,
                            const float* __restrict__ cm,
                            const float* __restrict__ w, const float* __restrict__ erev,
                            const float* __restrict__ mask,
                            const float* __restrict__ sw, const float* __restrict__ serev,
                            const float* __restrict__ smask) {
    int d = threadIdx.x;
    if (d >= Un) return;
    float nb = gleak[d] * vleak[d];
    float db = cm[d] * (float)NUNF + gleak[d] + EPSF;
    #pragma unroll 8
    for (int s = 0; s < Un; ++s) {
        int e = s*Un + d;
        float wm = 0.5f * w[e] * mask[e];
        nb += wm * erev[e]; db += wm;
    }
    #pragma unroll 8
    for (int s = 0; s < Sn; ++s) {
        int e = s*Un + d;
        float wm = 0.5f * sw[e] * smask[e];
        nb += wm * serev[e]; db += wm;
    }
    g_nbase[d] = nb;
    g_dbase[d] = db;
}

// ---- 2) sensory tanh sums: one warp per batch, lane = 4 dst ----
__global__ __launch_bounds__(1024, 1) void sensory_kernel(
    const float* __restrict__ inputs, const float* __restrict__ inw,
    const float* __restrict__ inb) {
    int warp = threadIdx.x >> 5, lane = threadIdx.x & 31;
    int b = blockIdx.x * 32 + warp;
    const float4* A4 = (const float4*)g_As;
    const float4* B4 = (const float4*)g_Bs;
    const float4* W4 = (const float4*)g_Ws;
    float4 num = make_float4(0.f,0.f,0.f,0.f);
    float4 den = make_float4(0.f,0.f,0.f,0.f);
    #pragma unroll 4
    for (int s = 0; s < Sn; ++s) {
        float x = fmaf(__ldg(inputs + b*Sn + s), __ldg(inw + s), __ldg(inb + s));
        float4 a  = A4[s*32 + lane];
        float4 bb = B4[s*32 + lane];
        float4 we = W4[s*32 + lane];
        float t;
        t = ftanh(fmaf(a.x, x, bb.x)); num.x = fmaf(t, we.x, num.x); den.x = fmaf(t, fabsf(we.x), den.x);
        t = ftanh(fmaf(a.y, x, bb.y)); num.y = fmaf(t, we.y, num.y); den.y = fmaf(t, fabsf(we.y), den.y);
        t = ftanh(fmaf(a.z, x, bb.z)); num.z = fmaf(t, we.z, num.z); den.z = fmaf(t, fabsf(we.z), den.z);
        t = ftanh(fmaf(a.w, x, bb.w)); num.w = fmaf(t, we.w, num.w); den.w = fmaf(t, fabsf(we.w), den.w);
    }
    ((float4*)g_snum)[b*32 + lane] = num;
    ((float4*)g_sden)[b*32 + lane] = den;
}

// ---- 3) main ODE kernel (half2 tanh) ----
#define NWARP 14
__global__ __launch_bounds__(NWARP*32, 1) void ltc_main(
    const float* __restrict__ state, const float* __restrict__ cm,
    const float* __restrict__ outw,  const float* __restrict__ outb,
    float* __restrict__ dout) {
    extern __shared__ unsigned smx[];
    uint4*    sAB = (uint4*)smx;                          // Un*32 uint4 = 64KB
    uint2*    sWp = (uint2*)(smx + Un*32*4);              // Un*32 uint2 = 32KB
    unsigned* sVh = smx + Un*32*4 + Un*32*2;              // NWARP*2*Un u32 = 14KB

    {   // cooperative SMEM fill
        const uint4* gAB = (const uint4*)g_ABh;
        const uint2* gW  = (const uint2*)g_Wh;
        for (int i = threadIdx.x; i < Un*32; i += NWARP*32) {
            sAB[i] = gAB[i]; sWp[i] = gW[i];
        }
    }
    __syncthreads();

    int warp = threadIdx.x >> 5, lane = threadIdx.x & 31;
    int start = (int)(((long long)blockIdx.x       * Bn) / gridDim.x);
    int end   = (int)(((long long)(blockIdx.x + 1) * Bn) / gridDim.x);
    int b0 = start + warp * 2;
    if (b0 >= end) return;
    int b1 = (b0 + 1 < end) ? (b0 + 1) : b0;
    bool has1 = (b0 + 1 < end);

    int d0 = lane * 4;
    float4 cm4 = *(const float4*)(cm      + d0);
    float4 nb4 = *(const float4*)(g_nbase + d0);
    float4 db4 = *(const float4*)(g_dbase + d0);
    float4 cmt;  cmt.x = cm4.x * (float)NUNF; cmt.y = cm4.y * (float)NUNF;
                 cmt.z = cm4.z * (float)NUNF; cmt.w = cm4.w * (float)NUNF;

    float4 sn0 = ((const float4*)g_snum)[b0*32 + lane];
    float4 sd0 = ((const float4*)g_sden)[b0*32 + lane];
    float4 sn1 = ((const float4*)g_snum)[b1*32 + lane];
    float4 sd1 = ((const float4*)g_sden)[b1*32 + lane];
    float4 nA, dA, nB, dB;
    nA.x = nb4.x + sn0.x; nA.y = nb4.y + sn0.y; nA.z = nb4.z + sn0.z; nA.w = nb4.w + sn0.w;
    dA.x = db4.x + sd0.x; dA.y = db4.y + sd0.y; dA.z = db4.z + sd0.z; dA.w = db4.w + sd0.w;
    nB.x = nb4.x + sn1.x; nB.y = nb4.y + sn1.y; nB.z = nb4.z + sn1.z; nB.w = nb4.w + sn1.w;
    dB.x = db4.x + sd1.x; dB.y = db4.y + sd1.y; dB.z = db4.z + sd1.z; dB.w = db4.w + sd1.w;

    float4 v0 = *(const float4*)(state + b0*Un + d0);
    float4 v1 = *(const float4*)(state + b1*Un + d0);
    unsigned* vp0 = sVh + (warp*2 + 0)*Un;
    unsigned* vp1 = sVh + (warp*2 + 1)*Un;
    vp0[d0+0] = splat_h(v0.x); vp0[d0+1] = splat_h(v0.y);
    vp0[d0+2] = splat_h(v0.z); vp0[d0+3] = splat_h(v0.w);
    vp1[d0+0] = splat_h(v1.x); vp1[d0+1] = splat_h(v1.y);
    vp1[d0+2] = splat_h(v1.z); vp1[d0+3] = splat_h(v1.w);
    __syncwarp();

    const __half2 h2z = __floats2half2_rn(0.f, 0.f);

    for (int it = 0; it < NUNF; ++it) {
        float4 num0 = nA, den0 = dA, num1 = nB, den1 = dB;
        for (int sc = 0; sc < Un; sc += 8) {
            // half2 chunk accumulators (2 batches x {num,den} x 2 dst-pairs)
            __half2 hn0a = h2z, hn0b = h2z, hd0a = h2z, hd0b = h2z;
            __half2 hn1a = h2z, hn1b = h2z, hd1a = h2z, hd1b = h2z;
            #pragma unroll
            for (int k = 0; k < 8; ++k) {
                int s = sc + k;
                __half2 vv0 = ash2(vp0[s]);
                __half2 vv1 = ash2(vp1[s]);
                uint4 ab = sAB[s*32 + lane];
                uint2 wp = sWp[s*32 + lane];
                __half2 a01 = ash2(ab.x), a23 = ash2(ab.y);
                __half2 b01 = ash2(ab.z), b23 = ash2(ab.w);
                __half2 w01 = ash2(wp.x), w23 = ash2(wp.y);
                __half2 wa01 = __habs2(w01), wa23 = __habs2(w23);
                __half2 t;
                t = tanh2(__hfma2(a01, vv0, b01));
                hn0a = __hfma2(t, w01, hn0a); hd0a = __hfma2(t, wa01, hd0a);
                t = tanh2(__hfma2(a23, vv0, b23));
                hn0b = __hfma2(t, w23, hn0b); hd0b = __hfma2(t, wa23, hd0b);
                t = tanh2(__hfma2(a01, vv1, b01));
                hn1a = __hfma2(t, w01, hn1a); hd1a = __hfma2(t, wa01, hd1a);
                t = tanh2(__hfma2(a23, vv1, b23));
                hn1b = __hfma2(t, w23, hn1b); hd1b = __hfma2(t, wa23, hd1b);
            }
            // fold chunk into fp32
            num0.x += __low2float(hn0a); num0.y += __high2float(hn0a);
            num0.z += __low2float(hn0b); num0.w += __high2float(hn0b);
            den0.x += __low2float(hd0a); den0.y += __high2float(hd0a);
            den0.z += __low2float(hd0b); den0.w += __high2float(hd0b);
            num1.x += __low2float(hn1a); num1.y += __high2float(hn1a);
            num1.z += __low2float(hn1b); num1.w += __high2float(hn1b);
            den1.x += __low2float(hd1a); den1.y += __high2float(hd1a);
            den1.z += __low2float(hd1b); den1.w += __high2float(hd1b);
        }
        float4 vn0, vn1;
        vn0.x = __fdividef(fmaf(cmt.x, v0.x, num0.x), den0.x);
        vn0.y = __fdividef(fmaf(cmt.y, v0.y, num0.y), den0.y);
        vn0.z = __fdividef(fmaf(cmt.z, v0.z, num0.z), den0.z);
        vn0.w = __fdividef(fmaf(cmt.w, v0.w, num0.w), den0.w);
        vn1.x = __fdividef(fmaf(cmt.x, v1.x, num1.x), den1.x);
        vn1.y = __fdividef(fmaf(cmt.y, v1.y, num1.y), den1.y);
        vn1.z = __fdividef(fmaf(cmt.z, v1.z, num1.z), den1.z);
        vn1.w = __fdividef(fmaf(cmt.w, v1.w, num1.w), den1.w);
        __syncwarp();
        vp0[d0+0] = splat_h(vn0.x); vp0[d0+1] = splat_h(vn0.y);
        vp0[d0+2] = splat_h(vn0.z); vp0[d0+3] = splat_h(vn0.w);
        vp1[d0+0] = splat_h(vn1.x); vp1[d0+1] = splat_h(vn1.y);
        vp1[d0+2] = splat_h(vn1.z); vp1[d0+3] = splat_h(vn1.w);
        __syncwarp();
        v0 = vn0; v1 = vn1;
    }

    // v section of output: [B*M, B*M + B*U)
    ((float4*)(dout + Bn*Mn + b0*Un))[lane] = v0;
    if (has1) ((float4*)(dout + Bn*Mn + b1*Un))[lane] = v1;
    // motor output: out = v[:, :M]*output_w + output_b
    if (d0 < Mn) {
        float4 ow = *(const float4*)(outw + d0);
        float4 ob = *(const float4*)(outb + d0);
        float4 o;
        o.x = fmaf(v0.x, ow.x, ob.x); o.y = fmaf(v0.y, ow.y, ob.y);
        o.z = fmaf(v0.z, ow.z, ob.z); o.w = fmaf(v0.w, ow.w, ob.w);
        ((float4*)(dout + b0*Mn))[lane] = o;
        if (has1) {
            o.x = fmaf(v1.x, ow.x, ob.x); o.y = fmaf(v1.y, ow.y, ob.y);
            o.z = fmaf(v1.z, ow.z, ob.z); o.w = fmaf(v1.w, ow.w, ob.w);
            ((float4*)(dout + b1*Mn))[lane] = o;
        }
    }
}

extern "C" void kernel_launch(void* const* d_in, const int* in_sizes, int n_in,
                              void* d_out, int out_size) {
    const float* inputs = (const float*)d_in[0];
    const float* state  = (const float*)d_in[1];
    const float* gleak  = (const float*)d_in[2];
    const float* vleak  = (const float*)d_in[3];
    const float* cm     = (const float*)d_in[4];
    const float* sigma  = (const float*)d_in[5];
    const float* mu     = (const float*)d_in[6];
    const float* w      = (const float*)d_in[7];
    const float* erev   = (const float*)d_in[8];
    const float* ssig   = (const float*)d_in[9];
    const float* smu    = (const float*)d_in[10];
    const float* sw     = (const float*)d_in[11];
    const float* serev  = (const float*)d_in[12];
    const float* mask   = (const float*)d_in[13];
    const float* smask  = (const float*)d_in[14];
    const float* inw    = (const float*)d_in[15];
    const float* inb    = (const float*)d_in[16];
    const float* outw   = (const float*)d_in[17];
    const float* outb   = (const float*)d_in[18];
    float* out = (float*)d_out;

    prep_kernel<<<32, 256>>>(sigma, mu, w, erev, mask, ssig, smu, sw, serev, smask);
    base_kernel<<<1, Un>>>(gleak, vleak, cm, w, erev, mask, sw, serev, smask);
    sensory_kernel<<<Bn/32, 1024>>>(inputs, inw, inb);

    size_t shmem = (size_t)(Un*32*4 + Un*32*2 + NWARP*2*Un) * sizeof(unsigned);  // ~110KB
    cudaFuncSetAttribute(ltc_main, cudaFuncAttributeMaxDynamicSharedMemorySize, (int)shmem);
    ltc_main<<<148, NWARP*32, shmem>>>(state, cm, outw, outb, out);
}

// round 4
// speedup vs baseline: 1.0687x; 1.0687x over previous
#include <cuda_runtime.h>

#define Bn 4096
#define Sn 64
#define Un 128
#define Mn 32
#define NUNF 6
#define EPSF 1e-8f

// ---- scratch (static device arrays; no allocation) ----
// sigmoid(sig*(v-mu)) = 0.5 + 0.5*tanh(0.5*sig*v - 0.5*sig*mu)
__device__ float g_A [Un*Un];   //  0.5*sigma              (row-major [s][d])
__device__ float g_Bc[Un*Un];   // -0.5*sigma*mu
__device__ float g_W [Un*Un];   //  0.5*w*mask*erev  (|.| = 0.5*w*mask)
__device__ float g_As[Sn*Un];
__device__ float g_Bs[Sn*Un];
__device__ float g_Ws[Sn*Un];
__device__ float g_nbase[Un];   // leak + 0.5*col-sums (rec + sensory)
__device__ float g_dbase[Un];   // cm*6 + gleak + eps + 0.5*col-sums |.|

__device__ __forceinline__ float ftanh(float x) {
    float t; asm("tanh.approx.f32 %0, %1;" : "=f"(t) : "f"(x));
    return t;
}

// ---- 1) setup: fold constants (blocks 0..63) + per-dst bases (block 64) ----
__global__ void setup_kernel(const float* __restrict__ sigma, const float* __restrict__ mu,
                             const float* __restrict__ w,     const float* __restrict__ erev,
                             const float* __restrict__ mask,
                             const float* __restrict__ ssig,  const float* __restrict__ smu,
                             const float* __restrict__ sw,    const float* __restrict__ serev,
                             const float* __restrict__ smask,
                             const float* __restrict__ gleak, const float* __restrict__ vleak,
                             const float* __restrict__ cm) {
    if (blockIdx.x < 64) {
        int i = blockIdx.x * 256 + threadIdx.x;
        if (i < Un*Un) {
            float s = 0.5f * sigma[i];
            g_A [i] = s;
            g_Bc[i] = -s * mu[i];
            g_W [i] = 0.5f * w[i] * mask[i] * erev[i];
        }
        if (i < Sn*Un) {
            float s = 0.5f * ssig[i];
            g_As[i] = s;
            g_Bs[i] = -s * smu[i];
            g_Ws[i] = 0.5f * sw[i] * smask[i] * serev[i];
        }
    } else {
        int d = threadIdx.x;
        if (d >= Un) return;
        float nb = gleak[d] * vleak[d];
        float db = cm[d] * (float)NUNF + gleak[d] + EPSF;
        #pragma unroll 8
        for (int s = 0; s < Un; ++s) {
            int e = s*Un + d;
            float wm = 0.5f * w[e] * mask[e];
            nb += wm * erev[e]; db += wm;
        }
        #pragma unroll 8
        for (int s = 0; s < Sn; ++s) {
            int e = s*Un + d;
            float wm = 0.5f * sw[e] * smask[e];
            nb += wm * serev[e]; db += wm;
        }
        g_nbase[d] = nb;
        g_dbase[d] = db;
    }
}

// ---- 2) main ODE kernel (fp32 tanh) ----
// 148 CTAs x 448 threads (14 warps). Each warp: 2 batch elements, sharing
// weight loads. lane owns dst 4*lane..4*lane+3. Sensory sums computed in a
// per-warp prologue (no separate kernel, no global round-trip).
#define NWARP 14
__global__ __launch_bounds__(NWARP*32, 1) void ltc_main(
    const float* __restrict__ inputs, const float* __restrict__ inw,
    const float* __restrict__ inb,
    const float* __restrict__ state,  const float* __restrict__ cm,
    const float* __restrict__ outw,   const float* __restrict__ outb,
    float* __restrict__ dout) {
    extern __shared__ float sm[];
    float4* sA = (float4*)sm;
    float4* sB = (float4*)(sm + Un*Un);
    float4* sW = (float4*)(sm + 2*Un*Un);
    float*  sV = sm + 3*Un*Un;              // NWARP * 2*Un floats (v or x staging)

    {   // cooperative SMEM fill (independent of everything below until sync)
        const float4* gA = (const float4*)g_A;
        const float4* gB = (const float4*)g_Bc;
        const float4* gW = (const float4*)g_W;
        for (int i = threadIdx.x; i < Un*Un/4; i += NWARP*32) {
            sA[i] = gA[i]; sB[i] = gB[i]; sW[i] = gW[i];
        }
    }

    int warp = threadIdx.x >> 5, lane = threadIdx.x & 31;
    int start = (int)(((long long)blockIdx.x       * Bn) / gridDim.x);
    int end   = (int)(((long long)(blockIdx.x + 1) * Bn) / gridDim.x);
    int b0 = start + warp * 2;
    bool active = (b0 < end);
    int b1 = b0, d0 = lane * 4;
    bool has1 = false;
    float* wsm = sV + warp * 2 * Un;        // this warp's 256-float scratch

    float4 nA = make_float4(0,0,0,0), dA = nA, nB = nA, dB = nA;
    float4 cmt = nA;

    if (active) {
        b1 = (b0 + 1 < end) ? (b0 + 1) : b0;
        has1 = (b0 + 1 < end);

        // ---- sensory prologue: x rows into warp scratch ----
        // wsm[0..63] = x(b0, s), wsm[64..127] = x(b1, s)
        if (lane < 16) {
            int s4 = lane * 4;
            float4 iw = *(const float4*)(inw + s4);
            float4 ib = *(const float4*)(inb + s4);
            float4 x0 = *(const float4*)(inputs + b0*Sn + s4);
            float4 x1 = *(const float4*)(inputs + b1*Sn + s4);
            float4 r0, r1;
            r0.x = fmaf(x0.x, iw.x, ib.x); r0.y = fmaf(x0.y, iw.y, ib.y);
            r0.z = fmaf(x0.z, iw.z, ib.z); r0.w = fmaf(x0.w, iw.w, ib.w);
            r1.x = fmaf(x1.x, iw.x, ib.x); r1.y = fmaf(x1.y, iw.y, ib.y);
            r1.z = fmaf(x1.z, iw.z, ib.z); r1.w = fmaf(x1.w, iw.w, ib.w);
            ((float4*)wsm)[lane]      = r0;
            ((float4*)(wsm + 64))[lane] = r1;
        }
        __syncwarp();

        const float4* A4 = (const float4*)g_As;
        const float4* B4 = (const float4*)g_Bs;
        const float4* W4 = (const float4*)g_Ws;
        #pragma unroll 4
        for (int s = 0; s < Sn; ++s) {
            float x0 = wsm[s], x1 = wsm[64 + s];
            float4 a  = A4[s*32 + lane];
            float4 bb = B4[s*32 + lane];
            float4 we = W4[s*32 + lane];
            float wax = fabsf(we.x), way = fabsf(we.y), waz = fabsf(we.z), waw = fabsf(we.w);
            float t;
            t = ftanh(fmaf(a.x, x0, bb.x)); nA.x = fmaf(t, we.x, nA.x); dA.x = fmaf(t, wax, dA.x);
            t = ftanh(fmaf(a.y, x0, bb.y)); nA.y = fmaf(t, we.y, nA.y); dA.y = fmaf(t, way, dA.y);
            t = ftanh(fmaf(a.z, x0, bb.z)); nA.z = fmaf(t, we.z, nA.z); dA.z = fmaf(t, waz, dA.z);
            t = ftanh(fmaf(a.w, x0, bb.w)); nA.w = fmaf(t, we.w, nA.w); dA.w = fmaf(t, waw, dA.w);
            t = ftanh(fmaf(a.x, x1, bb.x)); nB.x = fmaf(t, we.x, nB.x); dB.x = fmaf(t, wax, dB.x);
            t = ftanh(fmaf(a.y, x1, bb.y)); nB.y = fmaf(t, we.y, nB.y); dB.y = fmaf(t, way, dB.y);
            t = ftanh(fmaf(a.z, x1, bb.z)); nB.z = fmaf(t, we.z, nB.z); dB.z = fmaf(t, waz, dB.z);
            t = ftanh(fmaf(a.w, x1, bb.w)); nB.w = fmaf(t, we.w, nB.w); dB.w = fmaf(t, waw, dB.w);
        }

        float4 cm4 = *(const float4*)(cm      + d0);
        float4 nb4 = *(const float4*)(g_nbase + d0);
        float4 db4 = *(const float4*)(g_dbase + d0);
        cmt.x = cm4.x * (float)NUNF; cmt.y = cm4.y * (float)NUNF;
        cmt.z = cm4.z * (float)NUNF; cmt.w = cm4.w * (float)NUNF;
        nA.x += nb4.x; nA.y += nb4.y; nA.z += nb4.z; nA.w += nb4.w;
        nB.x += nb4.x; nB.y += nb4.y; nB.z += nb4.z; nB.w += nb4.w;
        dA.x += db4.x; dA.y += db4.y; dA.z += db4.z; dA.w += db4.w;
        dB.x += db4.x; dB.y += db4.y; dB.z += db4.z; dB.w += db4.w;
    }

    __syncthreads();   // weights resident (all threads participate)

    if (!active) return;

    // v state: interleaved pairs (v_b0[s], v_b1[s]) -> one LDS.64 broadcast
    float4 v0 = *(const float4*)(state + b0*Un + d0);
    float4 v1 = *(const float4*)(state + b1*Un + d0);
    float2* vp = (float2*)wsm;
    vp[d0+0] = make_float2(v0.x, v1.x);
    vp[d0+1] = make_float2(v0.y, v1.y);
    vp[d0+2] = make_float2(v0.z, v1.z);
    vp[d0+3] = make_float2(v0.w, v1.w);
    __syncwarp();

    for (int it = 0; it < NUNF; ++it) {
        float4 num0 = nA, den0 = dA, num1 = nB, den1 = dB;
        #pragma unroll 4
        for (int s = 0; s < Un; ++s) {
            float2 vs = vp[s];
            float4 a  = sA[s*32 + lane];
            float4 bb = sB[s*32 + lane];
            float4 we = sW[s*32 + lane];
            float wax = fabsf(we.x), way = fabsf(we.y), waz = fabsf(we.z), waw = fabsf(we.w);
            float t;
            t = ftanh(fmaf(a.x, vs.x, bb.x)); num0.x = fmaf(t, we.x, num0.x); den0.x = fmaf(t, wax, den0.x);
            t = ftanh(fmaf(a.y, vs.x, bb.y)); num0.y = fmaf(t, we.y, num0.y); den0.y = fmaf(t, way, den0.y);
            t = ftanh(fmaf(a.z, vs.x, bb.z)); num0.z = fmaf(t, we.z, num0.z); den0.z = fmaf(t, waz, den0.z);
            t = ftanh(fmaf(a.w, vs.x, bb.w)); num0.w = fmaf(t, we.w, num0.w); den0.w = fmaf(t, waw, den0.w);
            t = ftanh(fmaf(a.x, vs.y, bb.x)); num1.x = fmaf(t, we.x, num1.x); den1.x = fmaf(t, wax, den1.x);
            t = ftanh(fmaf(a.y, vs.y, bb.y)); num1.y = fmaf(t, we.y, num1.y); den1.y = fmaf(t, way, den1.y);
            t = ftanh(fmaf(a.z, vs.y, bb.z)); num1.z = fmaf(t, we.z, num1.z); den1.z = fmaf(t, waz, den1.z);
            t = ftanh(fmaf(a.w, vs.y, bb.w)); num1.w = fmaf(t, we.w, num1.w); den1.w = fmaf(t, waw, den1.w);
        }
        float4 vn0, vn1;
        vn0.x = fmaf(cmt.x, v0.x, num0.x) / den0.x;
        vn0.y = fmaf(cmt.y, v0.y, num0.y) / den0.y;
        vn0.z = fmaf(cmt.z, v0.z, num0.z) / den0.z;
        vn0.w = fmaf(cmt.w, v0.w, num0.w) / den0.w;
        vn1.x = fmaf(cmt.x, v1.x, num1.x) / den1.x;
        vn1.y = fmaf(cmt.y, v1.y, num1.y) / den1.y;
        vn1.z = fmaf(cmt.z, v1.z, num1.z) / den1.z;
        vn1.w = fmaf(cmt.w, v1.w, num1.w) / den1.w;
        __syncwarp();
        vp[d0+0] = make_float2(vn0.x, vn1.x);
        vp[d0+1] = make_float2(vn0.y, vn1.y);
        vp[d0+2] = make_float2(vn0.z, vn1.z);
        vp[d0+3] = make_float2(vn0.w, vn1.w);
        __syncwarp();
        v0 = vn0; v1 = vn1;
    }

    // v section of output: [B*M, B*M + B*U)
    ((float4*)(dout + Bn*Mn + b0*Un))[lane] = v0;
    if (has1) ((float4*)(dout + Bn*Mn + b1*Un))[lane] = v1;
    // motor output: out = v[:, :M]*output_w + output_b
    if (d0 < Mn) {
        float4 ow = *(const float4*)(outw + d0);
        float4 ob = *(const float4*)(outb + d0);
        float4 o;
        o.x = fmaf(v0.x, ow.x, ob.x); o.y = fmaf(v0.y, ow.y, ob.y);
        o.z = fmaf(v0.z, ow.z, ob.z); o.w = fmaf(v0.w, ow.w, ob.w);
        ((float4*)(dout + b0*Mn))[lane] = o;
        if (has1) {
            o.x = fmaf(v1.x, ow.x, ob.x); o.y = fmaf(v1.y, ow.y, ob.y);
            o.z = fmaf(v1.z, ow.z, ob.z); o.w = fmaf(v1.w, ow.w, ob.w);
            ((float4*)(dout + b1*Mn))[lane] = o;
        }
    }
}

extern "C" void kernel_launch(void* const* d_in, const int* in_sizes, int n_in,
                              void* d_out, int out_size) {
    const float* inputs = (const float*)d_in[0];
    const float* state  = (const float*)d_in[1];
    const float* gleak  = (const float*)d_in[2];
    const float* vleak  = (const float*)d_in[3];
    const float* cm     = (const float*)d_in[4];
    const float* sigma  = (const float*)d_in[5];
    const float* mu     = (const float*)d_in[6];
    const float* w      = (const float*)d_in[7];
    const float* erev   = (const float*)d_in[8];
    const float* ssig   = (const float*)d_in[9];
    const float* smu    = (const float*)d_in[10];
    const float* sw     = (const float*)d_in[11];
    const float* serev  = (const float*)d_in[12];
    const float* mask   = (const float*)d_in[13];
    const float* smask  = (const float*)d_in[14];
    const float* inw    = (const float*)d_in[15];
    const float* inb    = (const float*)d_in[16];
    const float* outw   = (const float*)d_in[17];
    const float* outb   = (const float*)d_in[18];
    float* out = (float*)d_out;

    setup_kernel<<<65, 256>>>(sigma, mu, w, erev, mask, ssig, smu, sw, serev, smask,
                              gleak, vleak, cm);

    size_t shmem = (size_t)(3*Un*Un + NWARP*2*Un) * sizeof(float);   // 192KB + 14KB
    cudaFuncSetAttribute(ltc_main, cudaFuncAttributeMaxDynamicSharedMemorySize, (int)shmem);
    ltc_main<<<148, NWARP*32, shmem>>>(inputs, inw, inb, state, cm, outw, outb, out);
}

// round 5
// speedup vs baseline: 1.1424x; 1.0690x over previous
#include <cuda_runtime.h>

#define Bn 4096
#define Sn 64
#define Un 128
#define Mn 32
#define NUNF 6
#define EPSF 1e-8f
#define NWARP 14
#define NTHR (NWARP*32)

__device__ __forceinline__ float ftanh(float x) {
    float t; asm("tanh.approx.f32 %0, %1;" : "=f"(t) : "f"(x));
    return t;
}

// Single fused kernel. 148 CTAs x 448 threads. Phases:
//  A1: fold sensory params (raw -> SMEM, 96KB region)
//  B : per-warp sensory tanh sums (+ threads<128: sensory column sums)
//  A2: fold recurrent params (raw -> same SMEM, overwrite, 192KB)
//  B2: threads<128 assemble nbase/dbase from column sums
//  C : 6-unfold dense ODE loop (MUFU-floor proven loop from R4)
__global__ __launch_bounds__(NTHR, 1) void ltc_all(
    const float* __restrict__ inputs, const float* __restrict__ state,
    const float* __restrict__ gleak,  const float* __restrict__ vleak,
    const float* __restrict__ cm,
    const float* __restrict__ sigma,  const float* __restrict__ mu,
    const float* __restrict__ w,      const float* __restrict__ erev,
    const float* __restrict__ ssig,   const float* __restrict__ smu,
    const float* __restrict__ sw,     const float* __restrict__ serev,
    const float* __restrict__ mask,   const float* __restrict__ smask,
    const float* __restrict__ inw,    const float* __restrict__ inb,
    const float* __restrict__ outw,   const float* __restrict__ outb,
    float* __restrict__ dout)
{
    extern __shared__ float sm[];
    float* sAf = sm;                       // Un*Un (a = 0.5*sigma)
    float* sBf = sm + Un*Un;               // Un*Un (b = -0.5*sigma*mu)
    float* sWf = sm + 2*Un*Un;             // Un*Un (we = 0.5*w*mask*erev)
    float* sV  = sm + 3*Un*Un;             // NWARP*2*Un scratch (x rows, then v)
    float* sSCn= sV + NWARP*2*Un;          // Un sensory col num-sums
    float* sSCd= sSCn + Un;                // Un sensory col den-sums
    float* sNB = sSCd + Un;                // Un nbase
    float* sDB = sNB + Un;                 // Un dbase

    int tid = threadIdx.x;

    // ---- Phase A1: fold sensory params into SMEM ----
    {
        const float4* s4 = (const float4*)ssig;
        const float4* m4 = (const float4*)smu;
        const float4* w4 = (const float4*)sw;
        const float4* e4 = (const float4*)serev;
        const float4* k4 = (const float4*)smask;
        for (int i = tid; i < Sn*Un/4; i += NTHR) {
            float4 sg = s4[i], mm = m4[i], ww = w4[i], ee = e4[i], kk = k4[i];
            float4 a, b, we;
            a.x = 0.5f*sg.x; a.y = 0.5f*sg.y; a.z = 0.5f*sg.z; a.w = 0.5f*sg.w;
            b.x = -a.x*mm.x; b.y = -a.y*mm.y; b.z = -a.z*mm.z; b.w = -a.w*mm.w;
            we.x = 0.5f*ww.x*kk.x*ee.x; we.y = 0.5f*ww.y*kk.y*ee.y;
            we.z = 0.5f*ww.z*kk.z*ee.z; we.w = 0.5f*ww.w*kk.w*ee.w;
            ((float4*)sAf)[i] = a; ((float4*)sBf)[i] = b; ((float4*)sWf)[i] = we;
        }
    }
    __syncthreads();

    int warp = tid >> 5, lane = tid & 31, d0 = lane * 4;
    int start = (int)(((long long)blockIdx.x       * Bn) / gridDim.x);
    int end   = (int)(((long long)(blockIdx.x + 1) * Bn) / gridDim.x);
    int b0 = start + warp * 2;
    bool active = (b0 < end);
    int b1 = b0;
    bool has1 = false;
    float* wsm = sV + warp * 2 * Un;

    float4 nA = make_float4(0,0,0,0), dA = nA, nB = nA, dB = nA;
    float4 cmt = nA;

    // ---- Phase B: per-warp sensory tanh sums (reads folded SMEM) ----
    if (active) {
        b1 = (b0 + 1 < end) ? (b0 + 1) : b0;
        has1 = (b0 + 1 < end);

        if (lane < 16) {
            int s4i = lane * 4;
            float4 iw = *(const float4*)(inw + s4i);
            float4 ib = *(const float4*)(inb + s4i);
            float4 x0 = *(const float4*)(inputs + b0*Sn + s4i);
            float4 x1 = *(const float4*)(inputs + b1*Sn + s4i);
            float4 r0, r1;
            r0.x = fmaf(x0.x, iw.x, ib.x); r0.y = fmaf(x0.y, iw.y, ib.y);
            r0.z = fmaf(x0.z, iw.z, ib.z); r0.w = fmaf(x0.w, iw.w, ib.w);
            r1.x = fmaf(x1.x, iw.x, ib.x); r1.y = fmaf(x1.y, iw.y, ib.y);
            r1.z = fmaf(x1.z, iw.z, ib.z); r1.w = fmaf(x1.w, iw.w, ib.w);
            ((float4*)wsm)[lane]        = r0;
            ((float4*)(wsm + 64))[lane] = r1;
        }
        __syncwarp();

        const float4* A4 = (const float4*)sAf;
        const float4* B4 = (const float4*)sBf;
        const float4* W4 = (const float4*)sWf;
        #pragma unroll 4
        for (int s = 0; s < Sn; ++s) {
            float x0 = wsm[s], x1 = wsm[64 + s];
            float4 a  = A4[s*32 + lane];
            float4 bb = B4[s*32 + lane];
            float4 we = W4[s*32 + lane];
            float wax = fabsf(we.x), way = fabsf(we.y), waz = fabsf(we.z), waw = fabsf(we.w);
            float t;
            t = ftanh(fmaf(a.x, x0, bb.x)); nA.x = fmaf(t, we.x, nA.x); dA.x = fmaf(t, wax, dA.x);
            t = ftanh(fmaf(a.y, x0, bb.y)); nA.y = fmaf(t, we.y, nA.y); dA.y = fmaf(t, way, dA.y);
            t = ftanh(fmaf(a.z, x0, bb.z)); nA.z = fmaf(t, we.z, nA.z); dA.z = fmaf(t, waz, dA.z);
            t = ftanh(fmaf(a.w, x0, bb.w)); nA.w = fmaf(t, we.w, nA.w); dA.w = fmaf(t, waw, dA.w);
            t = ftanh(fmaf(a.x, x1, bb.x)); nB.x = fmaf(t, we.x, nB.x); dB.x = fmaf(t, wax, dB.x);
            t = ftanh(fmaf(a.y, x1, bb.y)); nB.y = fmaf(t, we.y, nB.y); dB.y = fmaf(t, way, dB.y);
            t = ftanh(fmaf(a.z, x1, bb.z)); nB.z = fmaf(t, we.z, nB.z); dB.z = fmaf(t, waz, dB.z);
            t = ftanh(fmaf(a.w, x1, bb.w)); nB.w = fmaf(t, we.w, nB.w); dB.w = fmaf(t, waw, dB.w);
        }
    }
    // sensory column sums (threads 0..127; sWf sensory region stable this phase)
    if (tid < Un) {
        float n = 0.f, d = 0.f;
        #pragma unroll 8
        for (int s = 0; s < Sn; ++s) {
            float wv = sWf[s*Un + tid];
            n += wv; d += fabsf(wv);
        }
        sSCn[tid] = n; sSCd[tid] = d;
    }
    __syncthreads();

    // ---- Phase A2: fold recurrent params into SMEM (overwrite) ----
    {
        const float4* s4 = (const float4*)sigma;
        const float4* m4 = (const float4*)mu;
        const float4* w4 = (const float4*)w;
        const float4* e4 = (const float4*)erev;
        const float4* k4 = (const float4*)mask;
        for (int i = tid; i < Un*Un/4; i += NTHR) {
            float4 sg = s4[i], mm = m4[i], ww = w4[i], ee = e4[i], kk = k4[i];
            float4 a, b, we;
            a.x = 0.5f*sg.x; a.y = 0.5f*sg.y; a.z = 0.5f*sg.z; a.w = 0.5f*sg.w;
            b.x = -a.x*mm.x; b.y = -a.y*mm.y; b.z = -a.z*mm.z; b.w = -a.w*mm.w;
            we.x = 0.5f*ww.x*kk.x*ee.x; we.y = 0.5f*ww.y*kk.y*ee.y;
            we.z = 0.5f*ww.z*kk.z*ee.z; we.w = 0.5f*ww.w*kk.w*ee.w;
            ((float4*)sAf)[i] = a; ((float4*)sBf)[i] = b; ((float4*)sWf)[i] = we;
        }
    }
    __syncthreads();

    // ---- Phase B2: assemble nbase/dbase ----
    if (tid < Un) {
        float n = sSCn[tid], d = sSCd[tid];
        #pragma unroll 8
        for (int s = 0; s < Un; ++s) {
            float wv = sWf[s*Un + tid];
            n += wv; d += fabsf(wv);
        }
        float gl = gleak[tid];
        sNB[tid] = fmaf(gl, vleak[tid], n);
        sDB[tid] = cm[tid]*(float)NUNF + gl + EPSF + d;
    }
    __syncthreads();

    if (!active) return;

    // ---- Phase C: main ODE loop ----
    {
        float4 cm4 = *(const float4*)(cm  + d0);
        float4 nb4 = *(const float4*)(sNB + d0);
        float4 db4 = *(const float4*)(sDB + d0);
        cmt.x = cm4.x * (float)NUNF; cmt.y = cm4.y * (float)NUNF;
        cmt.z = cm4.z * (float)NUNF; cmt.w = cm4.w * (float)NUNF;
        nA.x += nb4.x; nA.y += nb4.y; nA.z += nb4.z; nA.w += nb4.w;
        nB.x += nb4.x; nB.y += nb4.y; nB.z += nb4.z; nB.w += nb4.w;
        dA.x += db4.x; dA.y += db4.y; dA.z += db4.z; dA.w += db4.w;
        dB.x += db4.x; dB.y += db4.y; dB.z += db4.z; dB.w += db4.w;
    }

    const float4* sA = (const float4*)sAf;
    const float4* sB = (const float4*)sBf;
    const float4* sW = (const float4*)sWf;

    float4 v0 = *(const float4*)(state + b0*Un + d0);
    float4 v1 = *(const float4*)(state + b1*Un + d0);
    float2* vp = (float2*)wsm;
    vp[d0+0] = make_float2(v0.x, v1.x);
    vp[d0+1] = make_float2(v0.y, v1.y);
    vp[d0+2] = make_float2(v0.z, v1.z);
    vp[d0+3] = make_float2(v0.w, v1.w);
    __syncwarp();

    for (int it = 0; it < NUNF; ++it) {
        float4 num0 = nA, den0 = dA, num1 = nB, den1 = dB;
        #pragma unroll 4
        for (int s = 0; s < Un; ++s) {
            float2 vs = vp[s];
            float4 a  = sA[s*32 + lane];
            float4 bb = sB[s*32 + lane];
            float4 we = sW[s*32 + lane];
            float wax = fabsf(we.x), way = fabsf(we.y), waz = fabsf(we.z), waw = fabsf(we.w);
            float t;
            t = ftanh(fmaf(a.x, vs.x, bb.x)); num0.x = fmaf(t, we.x, num0.x); den0.x = fmaf(t, wax, den0.x);
            t = ftanh(fmaf(a.y, vs.x, bb.y)); num0.y = fmaf(t, we.y, num0.y); den0.y = fmaf(t, way, den0.y);
            t = ftanh(fmaf(a.z, vs.x, bb.z)); num0.z = fmaf(t, we.z, num0.z); den0.z = fmaf(t, waz, den0.z);
            t = ftanh(fmaf(a.w, vs.x, bb.w)); num0.w = fmaf(t, we.w, num0.w); den0.w = fmaf(t, waw, den0.w);
            t = ftanh(fmaf(a.x, vs.y, bb.x)); num1.x = fmaf(t, we.x, num1.x); den1.x = fmaf(t, wax, den1.x);
            t = ftanh(fmaf(a.y, vs.y, bb.y)); num1.y = fmaf(t, we.y, num1.y); den1.y = fmaf(t, way, den1.y);
            t = ftanh(fmaf(a.z, vs.y, bb.z)); num1.z = fmaf(t, we.z, num1.z); den1.z = fmaf(t, waz, den1.z);
            t = ftanh(fmaf(a.w, vs.y, bb.w)); num1.w = fmaf(t, we.w, num1.w); den1.w = fmaf(t, waw, den1.w);
        }
        float4 vn0, vn1;
        vn0.x = fmaf(cmt.x, v0.x, num0.x) / den0.x;
        vn0.y = fmaf(cmt.y, v0.y, num0.y) / den0.y;
        vn0.z = fmaf(cmt.z, v0.z, num0.z) / den0.z;
        vn0.w = fmaf(cmt.w, v0.w, num0.w) / den0.w;
        vn1.x = fmaf(cmt.x, v1.x, num1.x) / den1.x;
        vn1.y = fmaf(cmt.y, v1.y, num1.y) / den1.y;
        vn1.z = fmaf(cmt.z, v1.z, num1.z) / den1.z;
        vn1.w = fmaf(cmt.w, v1.w, num1.w) / den1.w;
        __syncwarp();
        vp[d0+0] = make_float2(vn0.x, vn1.x);
        vp[d0+1] = make_float2(vn0.y, vn1.y);
        vp[d0+2] = make_float2(vn0.z, vn1.z);
        vp[d0+3] = make_float2(vn0.w, vn1.w);
        __syncwarp();
        v0 = vn0; v1 = vn1;
    }

    // v section of output: [B*M, B*M + B*U)
    ((float4*)(dout + Bn*Mn + b0*Un))[lane] = v0;
    if (has1) ((float4*)(dout + Bn*Mn + b1*Un))[lane] = v1;
    // motor output: out = v[:, :M]*output_w + output_b
    if (d0 < Mn) {
        float4 ow = *(const float4*)(outw + d0);
        float4 ob = *(const float4*)(outb + d0);
        float4 o;
        o.x = fmaf(v0.x, ow.x, ob.x); o.y = fmaf(v0.y, ow.y, ob.y);
        o.z = fmaf(v0.z, ow.z, ob.z); o.w = fmaf(v0.w, ow.w, ob.w);
        ((float4*)(dout + b0*Mn))[lane] = o;
        if (has1) {
            o.x = fmaf(v1.x, ow.x, ob.x); o.y = fmaf(v1.y, ow.y, ob.y);
            o.z = fmaf(v1.z, ow.z, ob.z); o.w = fmaf(v1.w, ow.w, ob.w);
            ((float4*)(dout + b1*Mn))[lane] = o;
        }
    }
}

extern "C" void kernel_launch(void* const* d_in, const int* in_sizes, int n_in,
                              void* d_out, int out_size) {
    const float* inputs = (const float*)d_in[0];
    const float* state  = (const float*)d_in[1];
    const float* gleak  = (const float*)d_in[2];
    const float* vleak  = (const float*)d_in[3];
    const float* cm     = (const float*)d_in[4];
    const float* sigma  = (const float*)d_in[5];
    const float* mu     = (const float*)d_in[6];
    const float* w      = (const float*)d_in[7];
    const float* erev   = (const float*)d_in[8];
    const float* ssig   = (const float*)d_in[9];
    const float* smu    = (const float*)d_in[10];
    const float* sw     = (const float*)d_in[11];
    const float* serev  = (const float*)d_in[12];
    const float* mask   = (const float*)d_in[13];
    const float* smask  = (const float*)d_in[14];
    const float* inw    = (const float*)d_in[15];
    const float* inb    = (const float*)d_in[16];
    const float* outw   = (const float*)d_in[17];
    const float* outb   = (const float*)d_in[18];
    float* out = (float*)d_out;

    size_t shmem = (size_t)(3*Un*Un + NWARP*2*Un + 4*Un) * sizeof(float);  // 208 KB
    cudaFuncSetAttribute(ltc_all, cudaFuncAttributeMaxDynamicSharedMemorySize, (int)shmem);
    ltc_all<<<148, NTHR, shmem>>>(inputs, state, gleak, vleak, cm,
                                  sigma, mu, w, erev, ssig, smu, sw, serev,
                                  mask, smask, inw, inb, outw, outb, out);
}